// round 1
// baseline (speedup 1.0000x reference)
#include <cuda_runtime.h>
#include <math.h>

#define BB   4
#define NPTS 4096
#define GG   4096
#define KNN  8
#define HH   64
#define EPSBN 1e-5f

// ---------------- scratch (static device globals; no allocations) ----------------
__device__ int   g_idx [BB*GG*KNN];
__device__ float g_vol [BB*HH*GG];     // buffer id 0
__device__ float g_tmp [BB*HH*GG];     // buffer id 1
__device__ float g_h1  [BB*HH*GG];     // buffer id 2
__device__ float g_vol8[BB*HH*512];    // buffer id 3
__device__ float g_mean[HH];
__device__ float g_rstd[HH];

__device__ __forceinline__ float* pick(int id) {
    switch (id) {
        case 0: return g_vol;
        case 1: return g_tmp;
        case 2: return g_h1;
        default: return g_vol8;
    }
}

__device__ __forceinline__ float gelu_tanh(float x) {
    // JAX default gelu (approximate=True)
    float x3 = x * x * x;
    float t  = tanhf(0.7978845608028654f * (x + 0.044715f * x3));
    return 0.5f * x * (1.0f + t);
}

// ---------------- KNN: per voxel, 8 nearest points ----------------
// 128 blocks (32 per batch) x 128 threads; each thread owns one voxel,
// scans all 4096 points via shared float4 tiles (x,y,z,|p|^2).
// Rank key e = |p|^2 - 2*g.p  (same ordering as reference d = |g|^2+|p|^2-2 g.p).
__global__ void knn_kernel(const float* __restrict__ pos) {
    __shared__ float4 tile[128];
    int b = blockIdx.x >> 5;
    int g = ((blockIdx.x & 31) * 128) + threadIdx.x;
    int gi = g >> 8, gj = (g >> 4) & 15, gk = g & 15;
    const float step = 2.0f / 15.0f;
    float gx = -1.0f + step * gi;
    float gy = -1.0f + step * gj;
    float gz = -1.0f + step * gk;
    float ax = -2.0f * gx, ay = -2.0f * gy, az = -2.0f * gz;

    float bd[KNN]; int bi[KNN];
#pragma unroll
    for (int j = 0; j < KNN; j++) { bd[j] = 3.4e38f; bi[j] = 0; }

    const float* pb = pos + (size_t)b * NPTS * 3;
    for (int t0 = 0; t0 < NPTS; t0 += 128) {
        __syncthreads();
        {
            int n = t0 + threadIdx.x;
            float px = pb[n * 3 + 0], py = pb[n * 3 + 1], pz = pb[n * 3 + 2];
            float pn = px * px + py * py + pz * pz;
            tile[threadIdx.x] = make_float4(px, py, pz, pn);
        }
        __syncthreads();
#pragma unroll 4
        for (int t = 0; t < 128; t++) {
            float4 p = tile[t];
            float e = fmaf(ax, p.x, fmaf(ay, p.y, fmaf(az, p.z, p.w)));
            if (e < bd[KNN - 1]) {
                int n = t0 + t;
#pragma unroll
                for (int j = KNN - 1; j >= 1; --j) {
                    if (e < bd[j - 1])      { bd[j] = bd[j - 1]; bi[j] = bi[j - 1]; }
                    else if (e < bd[j])     { bd[j] = e;         bi[j] = n; }
                }
                if (e < bd[0]) { bd[0] = e; bi[0] = n; }
            }
        }
    }
    int base = (b * GG + g) * KNN;
#pragma unroll
    for (int j = 0; j < KNN; j++) g_idx[base + j] = bi[j];
}

// ---------------- Bipartite conv MLP: per voxel features -> g_vol ----------------
// 4096 blocks x 256 threads; 4 voxels per block, 64 threads (=channels) per voxel.
// pe_w2 column kept in registers (reused 8x); up_w column loaded into same regs after.
__global__ void mlp_kernel(const float* __restrict__ pos, const float* __restrict__ xf,
                           const float* __restrict__ pe_w1, const float* __restrict__ pe_b1,
                           const float* __restrict__ pe_w2, const float* __restrict__ pe_b2,
                           const float* __restrict__ f_w,   const float* __restrict__ f_b,
                           const float* __restrict__ up_w,  const float* __restrict__ up_b) {
    __shared__ float s_w1[3 * 64], s_fw[3 * 64];
    __shared__ float s_b1[64], s_b2[64], s_fb[64], s_ub[64];
    __shared__ float s_t[4][64];

    int tid = threadIdx.x;
    int v = tid >> 6, h = tid & 63;

    if (tid < 192) { s_w1[tid] = pe_w1[tid]; s_fw[tid] = f_w[tid]; }
    if (tid < 64)  { s_b1[tid] = pe_b1[tid]; s_b2[tid] = pe_b2[tid];
                     s_fb[tid] = f_b[tid];   s_ub[tid] = up_b[tid]; }

    float wcol[64];
#pragma unroll
    for (int j = 0; j < 64; j++) wcol[j] = pe_w2[j * 64 + h];
    __syncthreads();

    int b = blockIdx.x >> 10;
    int g = ((blockIdx.x & 1023) << 2) + v;
    int gi = g >> 8, gj = (g >> 4) & 15, gk = g & 15;
    const float step = 2.0f / 15.0f;
    float gx = -1.0f + step * gi;
    float gy = -1.0f + step * gj;
    float gz = -1.0f + step * gk;

    const int* ib = g_idx + (b * GG + g) * KNN;
    float acc = 0.0f;

    for (int k = 0; k < KNN; k++) {
        int n = ib[k];
        const float* pp = pos + ((size_t)b * NPTS + n) * 3;
        float rx = pp[0] - gx, ry = pp[1] - gy, rz = pp[2] - gz;
        float t1 = rx * s_w1[h] + ry * s_w1[64 + h] + rz * s_w1[128 + h] + s_b1[h];
        s_t[v][h] = gelu_tanh(t1);
        __syncthreads();
        float pe = s_b2[h];
#pragma unroll
        for (int j = 0; j < 64; j++) pe = fmaf(s_t[v][j], wcol[j], pe);
        const float* xp = xf + ((size_t)b * NPTS + n) * 3;
        float fm = xp[0] * s_fw[h] + xp[1] * s_fw[64 + h] + xp[2] * s_fw[128 + h] + s_fb[h];
        acc = fmaf(pe, fm, acc);
        __syncthreads();
    }
    acc *= 0.125f;  // mean over K=8

#pragma unroll
    for (int j = 0; j < 64; j++) wcol[j] = up_w[j * 64 + h];
    s_t[v][h] = acc;
    __syncthreads();
    float o = s_ub[h];
#pragma unroll
    for (int j = 0; j < 64; j++) o = fmaf(s_t[v][j], wcol[j], o);
    o = gelu_tanh(o);

    // vol[b,c,z,y,x] = h[b, g=(x*16+y)*16+z, c]  -> s = z*256 + y*16 + x
    int s = (g & 15) * 256 + ((g >> 4) & 15) * 16 + (g >> 8);
    g_vol[(b * 64 + h) * GG + s] = o;
}

// ---------------- Conv3D 3x3x3 SAME, 64->64 channels ----------------
// Block: R*R threads (one per (z,y)), each computes an x-strip of R outputs
// for COP output channels. Input ci-slice staged in padded smem (no branches).
template <int R, int COP>
__global__ void conv3d_kernel(int in_id, const float* __restrict__ w,
                              const float* __restrict__ bias, int out_id) {
    constexpr int P = R + 2, S = R * R * R, NT = R * R;
    __shared__ float sl[P * P * P];
    __shared__ float wsh[COP * 64 * 27];

    const float* in = pick(in_id);
    float* out = pick(out_id);

    int tid = threadIdx.x;
    int co0 = blockIdx.x * COP;
    int b = blockIdx.y;

    for (int i = tid; i < COP * 64 * 27; i += NT) {
        int col = i / 1728, r = i - col * 1728;
        wsh[i] = w[(co0 + col) * 1728 + r];
    }
    for (int i = tid; i < P * P * P; i += NT) sl[i] = 0.0f;

    int z = tid / R, y = tid - z * R;
    float acc[COP][R];
#pragma unroll
    for (int c = 0; c < COP; c++)
#pragma unroll
        for (int xx = 0; xx < R; xx++) acc[c][xx] = 0.0f;

    for (int ci = 0; ci < 64; ci++) {
        __syncthreads();
        const float* ip = in + (size_t)(b * 64 + ci) * S;
        for (int i = tid; i < S; i += NT) {
            int zz = i / (R * R), rem = i - zz * (R * R);
            int yy = rem / R, xx = rem - yy * R;
            sl[(zz + 1) * P * P + (yy + 1) * P + (xx + 1)] = ip[i];
        }
        __syncthreads();
#pragma unroll
        for (int dz = 0; dz < 3; dz++) {
#pragma unroll
            for (int dy = 0; dy < 3; dy++) {
                const float* rowp = &sl[(z + dz) * P * P + (y + dy) * P];
                float r[R + 2];
#pragma unroll
                for (int xx = 0; xx < R + 2; xx++) r[xx] = rowp[xx];
#pragma unroll
                for (int c = 0; c < COP; c++) {
                    const float* wp = &wsh[c * 1728 + ci * 27 + (dz * 3 + dy) * 3];
                    float w0 = wp[0], w1 = wp[1], w2 = wp[2];
#pragma unroll
                    for (int xx = 0; xx < R; xx++)
                        acc[c][xx] = fmaf(w0, r[xx],
                                     fmaf(w1, r[xx + 1],
                                     fmaf(w2, r[xx + 2], acc[c][xx])));
                }
            }
        }
    }
#pragma unroll
    for (int c = 0; c < COP; c++) {
        float bv = bias[co0 + c];
        float* op = out + (size_t)(b * 64 + co0 + c) * S + z * R * R + y * R;
#pragma unroll
        for (int xx = 0; xx < R; xx++) op[xx] = acc[c][xx] + bv;
    }
}

// ---------------- BatchNorm statistics (training mode, per channel over B,spatial) -----
__global__ void bn_stats_kernel(int x_id, int S) {
    __shared__ float sh1[256], sh2[256];
    const float* x = pick(x_id);
    int c = blockIdx.x;
    int total = BB * S;
    float s1 = 0.0f, s2 = 0.0f;
    for (int i = threadIdx.x; i < total; i += 256) {
        int b = i / S, s = i - b * S;
        float v = x[(size_t)(b * 64 + c) * S + s];
        s1 += v; s2 += v * v;
    }
    sh1[threadIdx.x] = s1; sh2[threadIdx.x] = s2;
    __syncthreads();
    for (int off = 128; off > 0; off >>= 1) {
        if (threadIdx.x < off) {
            sh1[threadIdx.x] += sh1[threadIdx.x + off];
            sh2[threadIdx.x] += sh2[threadIdx.x + off];
        }
        __syncthreads();
    }
    if (threadIdx.x == 0) {
        float inv = 1.0f / (float)total;
        float m = sh1[0] * inv;
        float var = sh2[0] * inv - m * m;
        g_mean[c] = m;
        g_rstd[c] = rsqrtf(var + EPSBN);
    }
}

__global__ void norm_relu_kernel(int x_id, int y_id, int S) {
    const float* x = pick(x_id);
    float* y = pick(y_id);
    int n = BB * 64 * S;
    for (int i = blockIdx.x * blockDim.x + threadIdx.x; i < n; i += gridDim.x * blockDim.x) {
        int c = (i / S) & 63;
        float v = (x[i] - g_mean[c]) * g_rstd[c];
        y[i] = fmaxf(v, 0.0f);
    }
}

__global__ void norm_add_relu_kernel(int vol_id, int x_id, int S) {
    float* vol = pick(vol_id);
    const float* x = pick(x_id);
    int n = BB * 64 * S;
    for (int i = blockIdx.x * blockDim.x + threadIdx.x; i < n; i += gridDim.x * blockDim.x) {
        int c = (i / S) & 63;
        float v = vol[i] + (x[i] - g_mean[c]) * g_rstd[c];
        vol[i] = fmaxf(v, 0.0f);
    }
}

// ---------------- 2x2x2 max pool: g_vol (16^3) -> g_vol8 (8^3) ----------------
__global__ void maxpool_kernel() {
    int i = blockIdx.x * blockDim.x + threadIdx.x;
    if (i >= BB * 64 * 512) return;
    int x = i & 7, y = (i >> 3) & 7, z = (i >> 6) & 7, bc = i >> 9;
    const float* ip = g_vol + (size_t)bc * 4096;
    float m = -3.4e38f;
#pragma unroll
    for (int dz = 0; dz < 2; dz++)
#pragma unroll
        for (int dy = 0; dy < 2; dy++)
#pragma unroll
            for (int dx = 0; dx < 2; dx++)
                m = fmaxf(m, ip[(2 * z + dz) * 256 + (2 * y + dy) * 16 + (2 * x + dx)]);
    g_vol8[i] = m;
}

// ---------------- final BN affine + mean pool + linear head ----------------
__global__ void head_kernel(const float* __restrict__ on_g, const float* __restrict__ on_b,
                            const float* __restrict__ ro_w, const float* __restrict__ ro_b,
                            float* __restrict__ out) {
    __shared__ float sp[64];
    int b = blockIdx.x, c = threadIdx.x;
    const float* vp = g_vol8 + (size_t)(b * 64 + c) * 512;
    float s = 0.0f;
    for (int i = 0; i < 512; i++) s += vp[i];
    float pooled = (s * (1.0f / 512.0f) - g_mean[c]) * g_rstd[c] * on_g[c] + on_b[c];
    sp[c] = pooled;
    __syncthreads();
    if (c < 16) {
        float a = ro_b[c];
#pragma unroll
        for (int j = 0; j < 64; j++) a = fmaf(sp[j], ro_w[j * 16 + c], a);
        out[b * 16 + c] = a;
    }
}

// ---------------- launch ----------------
extern "C" void kernel_launch(void* const* d_in, const int* in_sizes, int n_in,
                              void* d_out, int out_size) {
    const float* pos   = (const float*)d_in[0];
    const float* xf    = (const float*)d_in[1];
    const float* pe_w1 = (const float*)d_in[2];
    const float* pe_b1 = (const float*)d_in[3];
    const float* pe_w2 = (const float*)d_in[4];
    const float* pe_b2 = (const float*)d_in[5];
    const float* f_w   = (const float*)d_in[6];
    const float* f_b   = (const float*)d_in[7];
    const float* up_w  = (const float*)d_in[8];
    const float* up_b  = (const float*)d_in[9];
    const float* conv_w= (const float*)d_in[10];
    const float* conv_b= (const float*)d_in[11];
    const float* on_g  = (const float*)d_in[12];
    const float* on_b  = (const float*)d_in[13];
    const float* ro_w  = (const float*)d_in[14];
    const float* ro_b  = (const float*)d_in[15];
    float* out = (float*)d_out;

    const int W1 = 64 * 64 * 27;  // per-conv weight count

    knn_kernel<<<128, 128>>>(pos);
    mlp_kernel<<<4096, 256>>>(pos, xf, pe_w1, pe_b1, pe_w2, pe_b2, f_w, f_b, up_w, up_b);

    // ---- residual block 0 (16^3) ----
    conv3d_kernel<16, 2><<<dim3(32, 4), 256>>>(0, conv_w + 0 * W1, conv_b + 0, 1);
    bn_stats_kernel<<<64, 256>>>(1, 4096);
    norm_relu_kernel<<<1024, 256>>>(1, 2, 4096);
    conv3d_kernel<16, 2><<<dim3(32, 4), 256>>>(2, conv_w + 1 * W1, conv_b + 64, 1);
    bn_stats_kernel<<<64, 256>>>(1, 4096);
    norm_add_relu_kernel<<<1024, 256>>>(0, 1, 4096);
    maxpool_kernel<<<512, 256>>>();

    // ---- residual block 1 (8^3) ----
    conv3d_kernel<8, 1><<<dim3(64, 4), 64>>>(3, conv_w + 2 * W1, conv_b + 128, 1);
    bn_stats_kernel<<<64, 256>>>(1, 512);
    norm_relu_kernel<<<128, 256>>>(1, 2, 512);
    conv3d_kernel<8, 1><<<dim3(64, 4), 64>>>(2, conv_w + 3 * W1, conv_b + 192, 1);
    bn_stats_kernel<<<64, 256>>>(1, 512);
    norm_add_relu_kernel<<<128, 256>>>(3, 1, 512);

    // ---- output norm + head ----
    bn_stats_kernel<<<64, 256>>>(3, 512);
    head_kernel<<<4, 64>>>(on_g, on_b, ro_w, ro_b, out);
}